// round 8
// baseline (speedup 1.0000x reference)
#include <cuda_runtime.h>
#include <cuda_bf16.h>

// patches: [B=2, N=49, C=8, P=256, P=256] fp32; out: [B, C, 1024, 1024] fp32.
// Inverse-gather: output (h,w) covered by tiles {h>>7-1, h>>7}x{w>>7-1, w>>7}
// clamped to [0,6]; count in {1,2,4}; out = sum / (count + 1e-8).
//
// Branch-free: always load 4 clamped candidate tiles, {0,1}-weighted FMA.
// Each thread produces 2 outputs (same (h,w); planes b=0 and b=1, same
// channel) -> 8 independent float4 loads in flight, ~55 regs, 4 CTAs/SM
// (50% occupancy). Persistent single-wave grid-stride.

namespace {
constexpr int NB = 2;
constexpr int NN = 49;
constexpr int NC = 8;
constexpr int PP = 256;
constexpr int HH = 1024;
constexpr int WW = 1024;
constexpr int TILES = 7;

constexpr int TOTAL_F4    = NB * NC * HH * WW / 4;  // 4,194,304
constexpr int HALF_F4     = TOTAL_F4 / 2;           // 2,097,152 (8 bc-planes)
constexpr int CH_F4       = PP * PP / 4;            // 16,384
constexpr int BATCH_F4    = NN * NC * CH_F4;
constexpr int N_STRIDE_F4 = NC * CH_F4;
}

__global__ __launch_bounds__(256, 4) void patch_merge_gather2(
    const float* __restrict__ patches, float* __restrict__ out)
{
    const float4* __restrict__ p4 = reinterpret_cast<const float4*>(patches);
    float4* __restrict__ o4 = reinterpret_cast<float4*>(out);

    const int stride = gridDim.x * blockDim.x;

    for (int idx = blockIdx.x * blockDim.x + threadIdx.x;
         idx < HALF_F4; idx += stride)
    {
        int w4  = idx & (WW / 4 - 1);   // 0..255
        int t   = idx >> 8;
        int h   = t & (HH - 1);         // 0..1023
        int c   = t >> 10;              // channel 0..7 (b=0 plane index)
        int w   = w4 << 2;

        int thh = h >> 7, tww = w >> 7;
        int th0 = thh - 1 < 0 ? 0 : thh - 1;
        int th1 = thh > TILES - 1 ? TILES - 1 : thh;
        int tw0 = tww - 1 < 0 ? 0 : tww - 1;
        int tw1 = tww > TILES - 1 ? TILES - 1 : tww;

        float wr = (th1 != th0) ? 1.f : 0.f;
        float wc = (tw1 != tw0) ? 1.f : 0.f;

        int ph0 = h - (th0 << 7), ph1 = h - (th1 << 7);
        int pw0 = w - (tw0 << 7), pw1 = w - (tw1 << 7);

        int s00 = (th0 * TILES + tw0) * N_STRIDE_F4 + ((ph0 * PP + pw0) >> 2);
        int s01 = (th0 * TILES + tw1) * N_STRIDE_F4 + ((ph0 * PP + pw1) >> 2);
        int s10 = (th1 * TILES + tw0) * N_STRIDE_F4 + ((ph1 * PP + pw0) >> 2);
        int s11 = (th1 * TILES + tw1) * N_STRIDE_F4 + ((ph1 * PP + pw1) >> 2);

        int plane0 = c * CH_F4;              // b = 0
        int plane1 = plane0 + BATCH_F4;      // b = 1

        // 8 independent streaming loads
        float4 v[8];
        v[0] = __ldcs(p4 + plane0 + s00);
        v[1] = __ldcs(p4 + plane0 + s01);
        v[2] = __ldcs(p4 + plane0 + s10);
        v[3] = __ldcs(p4 + plane0 + s11);
        v[4] = __ldcs(p4 + plane1 + s00);
        v[5] = __ldcs(p4 + plane1 + s01);
        v[6] = __ldcs(p4 + plane1 + s10);
        v[7] = __ldcs(p4 + plane1 + s11);

        float w01 = wc, w10 = wr, w11 = wr * wc;
        float cnt = (1.f + wr) * (1.f + wc);        // exactly 1, 2, or 4
        float inv = 1.f / (cnt + 1e-8f);

        #pragma unroll
        for (int k = 0; k < 2; ++k) {
            const float4* b = &v[4 * k];
            float4 a;
            a.x = (b[0].x + w01 * b[1].x + w10 * b[2].x + w11 * b[3].x) * inv;
            a.y = (b[0].y + w01 * b[1].y + w10 * b[2].y + w11 * b[3].y) * inv;
            a.z = (b[0].z + w01 * b[1].z + w10 * b[2].z + w11 * b[3].z) * inv;
            a.w = (b[0].w + w01 * b[1].w + w10 * b[2].w + w11 * b[3].w) * inv;
            __stcs(o4 + idx + k * HALF_F4, a);
        }
    }
}

extern "C" void kernel_launch(void* const* d_in, const int* in_sizes, int n_in,
                              void* d_out, int out_size)
{
    const float* patches = (const float*)d_in[0];
    float* out = (float*)d_out;

    int dev = 0, sms = 148, maxBlk = 0;
    cudaGetDevice(&dev);
    cudaDeviceGetAttribute(&sms, cudaDevAttrMultiProcessorCount, dev);
    cudaOccupancyMaxActiveBlocksPerMultiprocessor(
        &maxBlk, patch_merge_gather2, 256, 0);
    if (maxBlk < 1) maxBlk = 4;
    int grid = sms * maxBlk;                 // single balanced wave
    int maxGrid = (HALF_F4 + 255) / 256;
    if (grid > maxGrid) grid = maxGrid;

    patch_merge_gather2<<<grid, 256>>>(patches, out);
}